// round 16
// baseline (speedup 1.0000x reference)
#include <cuda_runtime.h>
#include <cuda_fp16.h>
#include <cstdint>
#include <math.h>

#define B_  2
#define S_  2048
#define H_  16
#define DH_ 64
#define D_  1024
#define M_  (B_*S_)   // 4096

// ---------------- scratch (__device__ globals; no allocation allowed) -------
__device__ __half g_xhi[M_*D_],  g_xlo[M_*D_];
__device__ __half g_qh[M_*D_];
__device__ __half g_kh[M_*D_];
__device__ __half g_vh[M_*D_];
__device__ __half g_ahi[M_*D_],  g_alo[M_*D_];
__device__ __half g_wqhi[D_*D_], g_wqlo[D_*D_];
__device__ __half g_wkhi[D_*D_], g_wklo[D_*D_];
__device__ __half g_wvhi[D_*D_], g_wvlo[D_*D_];
__device__ __half g_wohi[D_*D_], g_wolo[D_*D_];

// ---------------- helpers ----------------------------------------------------
__device__ __forceinline__ uint32_t smem_u32(const void* p) {
    uint32_t a;
    asm("{ .reg .u64 t; cvta.to.shared.u64 t, %1; cvt.u32.u64 %0, t; }"
        : "=r"(a) : "l"(p));
    return a;
}
__device__ __forceinline__ void cp_async16(uint32_t saddr, const void* gaddr) {
    asm volatile("cp.async.cg.shared.global [%0], [%1], 16;"
                 :: "r"(saddr), "l"(gaddr) : "memory");
}
#define CP_COMMIT() asm volatile("cp.async.commit_group;" ::: "memory")
#define CP_WAIT(n)  asm volatile("cp.async.wait_group %0;" :: "n"(n) : "memory")

__device__ __forceinline__ void ldsm_x4(uint32_t* r, uint32_t addr) {
    asm volatile("ldmatrix.sync.aligned.m8n8.x4.shared.b16 {%0,%1,%2,%3}, [%4];"
                 : "=r"(r[0]), "=r"(r[1]), "=r"(r[2]), "=r"(r[3]) : "r"(addr));
}
__device__ __forceinline__ void ldsm_x4t(uint32_t* r, uint32_t addr) {
    asm volatile("ldmatrix.sync.aligned.m8n8.x4.trans.shared.b16 {%0,%1,%2,%3}, [%4];"
                 : "=r"(r[0]), "=r"(r[1]), "=r"(r[2]), "=r"(r[3]) : "r"(addr));
}
__device__ __forceinline__ void mma_f16(float* c, const uint32_t* a, const uint32_t* b) {
    asm volatile(
        "mma.sync.aligned.m16n8k16.row.col.f32.f16.f16.f32 "
        "{%0,%1,%2,%3}, {%4,%5,%6,%7}, {%8,%9}, {%0,%1,%2,%3};"
        : "+f"(c[0]), "+f"(c[1]), "+f"(c[2]), "+f"(c[3])
        : "r"(a[0]), "r"(a[1]), "r"(a[2]), "r"(a[3]), "r"(b[0]), "r"(b[1]));
}
__device__ __forceinline__ float ex2f(float x) {
    float r;
    asm("ex2.approx.f32 %0, %1;" : "=f"(r) : "f"(x));
    return r;
}
__device__ __forceinline__ uint32_t ex2_h2(uint32_t x) {
    uint32_t r;
    asm("ex2.approx.f16x2 %0, %1;" : "=r"(r) : "r"(x));
    return r;
}
__device__ __forceinline__ uint32_t hfma2(uint32_t a, uint32_t b, uint32_t c) {
    uint32_t r;
    asm("fma.rn.f16x2 %0, %1, %2, %3;" : "=r"(r) : "r"(a), "r"(b), "r"(c));
    return r;
}
__device__ __forceinline__ uint32_t hsub2(uint32_t a, uint32_t b) {
    uint32_t r;
    asm("sub.f16x2 %0, %1, %2;" : "=r"(r) : "r"(a), "r"(b));
    return r;
}
__device__ __forceinline__ uint32_t hmax2(uint32_t a, uint32_t b) {
    uint32_t r;
    asm("max.f16x2 %0, %1, %2;" : "=r"(r) : "r"(a), "r"(b));
    return r;
}
__device__ __forceinline__ void split2h(float x0, float x1, uint32_t& hi, uint32_t& lo) {
    __half h0 = __float2half_rn(x0);
    __half h1 = __float2half_rn(x1);
    __half l0 = __float2half_rn(x0 - __half2float(h0));
    __half l1 = __float2half_rn(x1 - __half2float(h1));
    hi = (uint32_t)__half_as_ushort(h0) | ((uint32_t)__half_as_ushort(h1) << 16);
    lo = (uint32_t)__half_as_ushort(l0) | ((uint32_t)__half_as_ushort(l1) << 16);
}
__device__ __forceinline__ uint32_t pack2h(float x0, float x1) {
    uint32_t r;
    asm("cvt.rn.f16x2.f32 %0, %1, %2;" : "=r"(r) : "f"(x1), "f"(x0));
    return r;
}

// ---------------- conversions --------------------------------------------------
__global__ __launch_bounds__(256) void conv_split(
    const float* __restrict__ x, __half* __restrict__ hi,
    __half* __restrict__ lo, int n4)
{
    int i = blockIdx.x * blockDim.x + threadIdx.x;
    if (i >= n4) return;
    float4 v = ((const float4*)x)[i];
    uint32_t h0, l0, h1, l1;
    split2h(v.x, v.y, h0, l0);
    split2h(v.z, v.w, h1, l1);
    uint2 ho = { h0, h1 }, loo = { l0, l1 };
    ((uint2*)hi)[i] = ho;
    ((uint2*)lo)[i] = loo;
}

__global__ __launch_bounds__(256) void conv_split_w(
    const float* w0, const float* w1, const float* w2, const float* w3,
    __half* h0, __half* l0, __half* h1, __half* l1,
    __half* h2, __half* l2, __half* h3, __half* l3)
{
    const float* x; __half* hi; __half* lo;
    if      (blockIdx.y == 0) { x = w0; hi = h0; lo = l0; }
    else if (blockIdx.y == 1) { x = w1; hi = h1; lo = l1; }
    else if (blockIdx.y == 2) { x = w2; hi = h2; lo = l2; }
    else                      { x = w3; hi = h3; lo = l3; }
    int i = blockIdx.x * blockDim.x + threadIdx.x;
    if (i >= D_*D_/4) return;
    float4 v = ((const float4*)x)[i];
    uint32_t a0, b0, a1, b1;
    split2h(v.x, v.y, a0, b0);
    split2h(v.z, v.w, a1, b1);
    uint2 ho = { a0, a1 }, loo = { b0, b1 };
    ((uint2*)hi)[i] = ho;
    ((uint2*)lo)[i] = loo;
}

// ---------------- mma.sync 3-pass fp16 GEMM v4: BK=64, NKT=16 -----------------
// C[M][N] = A[M][K] @ W[N][K]^T + bias.  A and W split hi/lo.
// C = Ahi*Whi + Ahi*Wlo + Alo*Whi  (fp32 accum).
// 512 threads, 16 warps (4m x 4n), warp 32x32, BK=64 halves (128B rows),
// double-buffered cp.async (NSTAGE=2), SW128-style row swizzle (chunk ^= row&7).
// Halves the k-iteration count (32 -> 16): attacks per-iteration overhead.
#define BKH     64
#define MAT_B   (128*128)           // 16384 B per matrix per stage
#define STAGE_B (4*MAT_B)           // 65536
#define NSTAGE  2
#define GEMM_SMEM (NSTAGE*STAGE_B)  // 131072

template <int MODE>
__global__ __launch_bounds__(512, 1) void gemm_mma_split(
    const __half* __restrict__ Ahi, const __half* __restrict__ Alo,
    const __half* __restrict__ Wh0, const __half* __restrict__ Wl0,
    const __half* __restrict__ Wh1, const __half* __restrict__ Wl1,
    const __half* __restrict__ Wh2, const __half* __restrict__ Wl2,
    const float* __restrict__ b0p, const float* __restrict__ b1p,
    const float* __restrict__ b2p,
    float* __restrict__ C,
    __half* __restrict__ C0, __half* __restrict__ C1, __half* __restrict__ C2)
{
    const __half* Whi; const __half* Wlo; const float* bias; __half* Ch;
    if      (blockIdx.z == 0) { Whi = Wh0; Wlo = Wl0; bias = b0p; Ch = C0; }
    else if (blockIdx.z == 1) { Whi = Wh1; Wlo = Wl1; bias = b1p; Ch = C1; }
    else                      { Whi = Wh2; Wlo = Wl2; bias = b2p; Ch = C2; }

    extern __shared__ __align__(1024) char smraw[];
    const uint32_t sb = smem_u32(smraw);

    const int tid = threadIdx.x;
    const int wid = tid >> 5;
    const int l   = tid & 31;
    const int wm  = wid & 3;
    const int wn  = wid >> 2;
    const int m0  = blockIdx.y * 128;
    const int n0  = blockIdx.x * 128;

    // copy mapping: row = tid>>2 (0..127); thread owns chunks (tid&3) and (tid&3)+4
    const int crow = tid >> 2;
    const int c1   = tid & 3;
    const int xr   = crow & 7;
    const uint32_t so1 = (uint32_t)(crow * 128 + (((c1    ) ^ xr) << 4));
    const uint32_t so2 = (uint32_t)(crow * 128 + (((c1 + 4) ^ xr) << 4));
    const __half* gAh = Ahi + (size_t)(m0 + crow) * D_ + c1 * 8;
    const __half* gAl = Alo + (size_t)(m0 + crow) * D_ + c1 * 8;
    const __half* gWh = Whi + (size_t)(n0 + crow) * D_ + c1 * 8;
    const __half* gWl = Wlo + (size_t)(n0 + crow) * D_ + c1 * 8;

    // ldsm row bases (swizzle: chunk ^= row&7; mt/np strides of 16 rows keep
    // row&7 unchanged -> second fragments at flat +2048B)
    const int rA = wm * 32 + (l & 15);
    const int xA = rA & 7;
    const int cA = l >> 4;                 // 0..1
    const uint32_t rowA = (uint32_t)(rA * 128);
    const int rB = wn * 32 + (l & 7) + ((l >> 4) << 3);
    const int xB = rB & 7;
    const int cB = (l >> 3) & 1;
    const uint32_t rowB = (uint32_t)(rB * 128);

    float acc[2][4][4];
#pragma unroll
    for (int mt = 0; mt < 2; mt++)
#pragma unroll
        for (int nt = 0; nt < 4; nt++)
#pragma unroll
            for (int e = 0; e < 4; e++) acc[mt][nt][e] = 0.f;

    const int NKT = D_ / BKH;   // 16

    auto issue_stage = [&](int s) {
        const uint32_t d = sb + (s & 1) * STAGE_B;
        const int off = s * BKH;
        cp_async16(d + 0*MAT_B + so1, gAh + off);
        cp_async16(d + 0*MAT_B + so2, gAh + off + 32);
        cp_async16(d + 1*MAT_B + so1, gAl + off);
        cp_async16(d + 1*MAT_B + so2, gAl + off + 32);
        cp_async16(d + 2*MAT_B + so1, gWh + off);
        cp_async16(d + 2*MAT_B + so2, gWh + off + 32);
        cp_async16(d + 3*MAT_B + so1, gWl + off);
        cp_async16(d + 3*MAT_B + so2, gWl + off + 32);
    };

    issue_stage(0); CP_COMMIT();

    for (int kt = 0; kt < NKT; kt++) {
        if (kt + 1 < NKT) {
            issue_stage(kt + 1);
            CP_COMMIT();
            CP_WAIT(1);          // stage kt complete
        } else {
            CP_WAIT(0);
        }
        __syncthreads();

        const uint32_t base = sb + (kt & 1) * STAGE_B;

#pragma unroll
        for (int kk = 0; kk < 4; kk++) {
            const uint32_t aA = base + rowA + (uint32_t)((((2*kk + cA) ^ xA)) << 4);
            const uint32_t aB = base + rowB + (uint32_t)((((2*kk + cB) ^ xB)) << 4);

            uint32_t ah[2][4];
            ldsm_x4(ah[0], aA + 0*MAT_B);
            ldsm_x4(ah[1], aA + 0*MAT_B + 2048);
            uint32_t wh[2][4];
            ldsm_x4(wh[0], aB + 2*MAT_B);
            ldsm_x4(wh[1], aB + 2*MAT_B + 2048);
#pragma unroll
            for (int mt = 0; mt < 2; mt++)
#pragma unroll
                for (int nt = 0; nt < 4; nt++)
                    mma_f16(acc[mt][nt], ah[mt], &wh[nt >> 1][(nt & 1) * 2]);

            uint32_t wl[2][4];
            ldsm_x4(wl[0], aB + 3*MAT_B);
            ldsm_x4(wl[1], aB + 3*MAT_B + 2048);
#pragma unroll
            for (int mt = 0; mt < 2; mt++)
#pragma unroll
                for (int nt = 0; nt < 4; nt++)
                    mma_f16(acc[mt][nt], ah[mt], &wl[nt >> 1][(nt & 1) * 2]);

            uint32_t al[2][4];
            ldsm_x4(al[0], aA + 1*MAT_B);
            ldsm_x4(al[1], aA + 1*MAT_B + 2048);
#pragma unroll
            for (int mt = 0; mt < 2; mt++)
#pragma unroll
                for (int nt = 0; nt < 4; nt++)
                    mma_f16(acc[mt][nt], al[mt], &wh[nt >> 1][(nt & 1) * 2]);
        }

        __syncthreads();
    }

    const int rbase = m0 + wm*32 + (l >> 2);
    const int cbase = n0 + wn*32 + (l & 3) * 2;
#pragma unroll
    for (int mt = 0; mt < 2; mt++) {
#pragma unroll
        for (int nt = 0; nt < 4; nt++) {
            const int col = cbase + nt * 8;
            const float b0 = bias[col], b1 = bias[col + 1];
            const size_t r0o = (size_t)(rbase + mt*16) * D_ + col;
            const size_t r1o = (size_t)(rbase + mt*16 + 8) * D_ + col;
            if (MODE == 1) {
                *(uint32_t*)(Ch + r0o) = pack2h(acc[mt][nt][0] + b0, acc[mt][nt][1] + b1);
                *(uint32_t*)(Ch + r1o) = pack2h(acc[mt][nt][2] + b0, acc[mt][nt][3] + b1);
            } else {
                float2 v0 = { acc[mt][nt][0] + b0, acc[mt][nt][1] + b1 };
                float2 v1 = { acc[mt][nt][2] + b0, acc[mt][nt][3] + b1 };
                *(float2*)(C + r0o) = v0;
                *(float2*)(C + r1o) = v1;
            }
        }
    }
}

// ---------------- fp16 flash attention (R15, frozen) ---------------------------
#define AT_QP 72
#define oQ 0
#define oK 18432
#define oV 36864
#define oM 55296
#define ATT_SMEM (oM + S_*2)   // 59392

__global__ __launch_bounds__(256, 2) void attn_mma(
    const __half* __restrict__ Qh, const __half* __restrict__ Kh,
    const __half* __restrict__ Vh, const int* __restrict__ mask,
    __half* __restrict__ Ah, __half* __restrict__ Al)
{
    extern __shared__ __align__(1024) char sm[];
    const uint32_t sb = smem_u32(sm);
    uint32_t* Mh2 = (uint32_t*)(sm + oM);

    const int tid = threadIdx.x;
    const int wid = tid >> 5;
    const int l   = tid & 31;
    const int b   = blockIdx.y >> 4;
    const int h   = blockIdx.y & 15;
    const int q0  = blockIdx.x * 128;

    const int crow = tid >> 1, chc = (tid & 1) * 32;
    const uint32_t cds = (uint32_t)(crow * AT_QP + chc) * 2;
    const size_t gKVrow = (size_t)(b*S_ + crow) * D_ + h*DH_ + chc;

    auto issue_K = [&](int kt) {
        const size_t g = gKVrow + (size_t)kt * 128 * D_;
#pragma unroll
        for (int j = 0; j < 4; j++)
            cp_async16(sb + oK + cds + j*16, Kh + g + j*8);
    };
    auto issue_V = [&](int kt) {
        const size_t g = gKVrow + (size_t)kt * 128 * D_;
#pragma unroll
        for (int j = 0; j < 4; j++)
            cp_async16(sb + oV + cds + j*16, Vh + g + j*8);
    };

    for (int i = tid; i < S_/2; i += 256) {
        const int2 mv = *(const int2*)(mask + (size_t)b*S_ + 2*i);
        uint32_t w = (mv.x ? 0u : 0xFC00u) | ((mv.y ? 0u : 0xFC00u) << 16);
        Mh2[i] = w;
    }

    {
        const size_t g = (size_t)(b*S_ + q0 + crow) * D_ + h*DH_ + chc;
#pragma unroll
        for (int j = 0; j < 4; j++)
            cp_async16(sb + oQ + cds + j*16, Qh + g + j*8);
    }
    issue_K(0);
    CP_COMMIT();
    issue_V(0);
    CP_COMMIT();

    float m_run[2] = { -1e30f, -1e30f };
    float o[8][4];
    float o_sum[4] = { 0.f, 0.f, 0.f, 0.f };
#pragma unroll
    for (int nt = 0; nt < 8; nt++)
#pragma unroll
        for (int e = 0; e < 4; e++) o[nt][e] = 0.f;

    const uint32_t ones2[2] = { 0x3C003C00u, 0x3C003C00u };

    const uint32_t aQ  = sb + oQ + (uint32_t)(((wid<<4) + (l & 15)) * AT_QP + ((l >> 4) << 3)) * 2;
    const uint32_t aKo = (uint32_t)(((l & 7) + ((l >> 4) << 3)) * AT_QP + (((l >> 3) & 1) << 3)) * 2;
    const uint32_t aVo = (uint32_t)(((l & 7) + (((l >> 3) & 1) << 3)) * AT_QP + ((l >> 4) << 3)) * 2;

    const float KSC = 0.125f * 1.44269504f;
    const uint32_t KSC2 = pack2h(KSC, KSC);

    for (int kt = 0; kt < S_/128; kt++) {
        CP_WAIT(1);
        __syncthreads();

        float s[16][4];
#pragma unroll
        for (int nt = 0; nt < 16; nt++)
#pragma unroll
            for (int e = 0; e < 4; e++) s[nt][e] = 0.f;

#pragma unroll
        for (int ks = 0; ks < 4; ks++) {
            uint32_t q[4];
            ldsm_x4(q, aQ + ks*32);
#pragma unroll
            for (int np = 0; np < 8; np++) {
                uint32_t k[4];
                ldsm_x4(k, sb + oK + aKo + np*(16*AT_QP*2) + ks*32);
                mma_f16(s[2*np],   q, k);
                mma_f16(s[2*np+1], q, k+2);
            }
        }

        const int mb = kt * 64 + (l & 3);
        uint32_t pw[16][2];
        uint32_t mxp0 = 0xFC00FC00u, mxp1 = 0xFC00FC00u;
#pragma unroll
        for (int nt = 0; nt < 16; nt++) {
            const uint32_t m2 = Mh2[mb + nt*4];
            uint32_t w0 = pack2h(s[nt][0], s[nt][1]);
            uint32_t w1 = pack2h(s[nt][2], s[nt][3]);
            w0 = hfma2(w0, KSC2, m2);
            w1 = hfma2(w1, KSC2, m2);
            mxp0 = hmax2(mxp0, w0);
            mxp1 = hmax2(mxp1, w1);
            pw[nt][0] = w0;
            pw[nt][1] = w1;
        }
        __half2 hx0 = *reinterpret_cast<__half2*>(&mxp0);
        __half2 hx1 = *reinterpret_cast<__half2*>(&mxp1);
        float mx0 = fmaxf(__low2float(hx0), __high2float(hx0));
        float mx1 = fmaxf(__low2float(hx1), __high2float(hx1));
        mx0 = fmaxf(mx0, __shfl_xor_sync(0xffffffffu, mx0, 1));
        mx0 = fmaxf(mx0, __shfl_xor_sync(0xffffffffu, mx0, 2));
        mx1 = fmaxf(mx1, __shfl_xor_sync(0xffffffffu, mx1, 1));
        mx1 = fmaxf(mx1, __shfl_xor_sync(0xffffffffu, mx1, 2));

        const float mn0 = fmaxf(m_run[0], mx0);
        const float mn1 = fmaxf(m_run[1], mx1);
        const float al0 = ex2f(m_run[0] - mn0);
        const float al1 = ex2f(m_run[1] - mn1);
        m_run[0] = mn0; m_run[1] = mn1;

        const uint32_t mn0h = pack2h(mn0, mn0);
        const uint32_t mn1h = pack2h(mn1, mn1);
#pragma unroll
        for (int nt = 0; nt < 16; nt++) {
            pw[nt][0] = ex2_h2(hsub2(pw[nt][0], mn0h));
            pw[nt][1] = ex2_h2(hsub2(pw[nt][1], mn1h));
        }

#pragma unroll
        for (int nt = 0; nt < 8; nt++) {
            o[nt][0] *= al0; o[nt][1] *= al0;
            o[nt][2] *= al1; o[nt][3] *= al1;
        }
        o_sum[0] *= al0; o_sum[1] *= al0;
        o_sum[2] *= al1; o_sum[3] *= al1;

        CP_WAIT(0);
        __syncthreads();

        if (kt + 1 < S_/128) issue_K(kt + 1);
        CP_COMMIT();

#pragma unroll
        for (int ks = 0; ks < 8; ks++) {
            uint32_t p[4] = { pw[2*ks][0], pw[2*ks][1], pw[2*ks+1][0], pw[2*ks+1][1] };
            mma_f16(o_sum, p, ones2);
#pragma unroll
            for (int vb = 0; vb < 4; vb++) {
                uint32_t v[4];
                ldsm_x4t(v, sb + oV + aVo + ks*(16*AT_QP*2) + vb*32);
                mma_f16(o[2*vb],   p, v);
                mma_f16(o[2*vb+1], p, v+2);
            }
        }

        __syncthreads();
        if (kt + 1 < S_/128) issue_V(kt + 1);
        CP_COMMIT();
    }

    const float i0 = 1.f / o_sum[0];
    const float i1 = 1.f / o_sum[2];
    const int   c0 = (l & 3) * 2;
    const size_t row0 = (size_t)(b*S_ + q0 + (wid<<4) + (l >> 2));
    const size_t row1 = row0 + 8;
#pragma unroll
    for (int nt = 0; nt < 8; nt++) {
        const int col = h*DH_ + nt*8 + c0;
        uint32_t hi, lo;
        split2h(o[nt][0]*i0, o[nt][1]*i0, hi, lo);
        *(uint32_t*)(Ah + row0*D_ + col) = hi;
        *(uint32_t*)(Al + row0*D_ + col) = lo;
        split2h(o[nt][2]*i1, o[nt][3]*i1, hi, lo);
        *(uint32_t*)(Ah + row1*D_ + col) = hi;
        *(uint32_t*)(Al + row1*D_ + col) = lo;
    }
}

// ---------------------------------------------------------------------------
extern "C" void kernel_launch(void* const* d_in, const int* in_sizes, int n_in,
                              void* d_out, int out_size)
{
    const float* x    = (const float*)d_in[0];
    const int*   mask = (const int*)  d_in[1];
    const float* Wq   = (const float*)d_in[2];
    const float* bq   = (const float*)d_in[3];
    const float* Wk   = (const float*)d_in[4];
    const float* bk   = (const float*)d_in[5];
    const float* Wv   = (const float*)d_in[6];
    const float* bv   = (const float*)d_in[7];
    const float* Wo   = (const float*)d_in[8];
    const float* bo   = (const float*)d_in[9];
    float* out = (float*)d_out;

    __half *xhi, *xlo, *qh, *kh, *vh, *ahi, *alo;
    __half *wqh, *wql, *wkh, *wkl, *wvh, *wvl, *woh, *wol;
    cudaGetSymbolAddress((void**)&xhi, g_xhi);
    cudaGetSymbolAddress((void**)&xlo, g_xlo);
    cudaGetSymbolAddress((void**)&qh,  g_qh);
    cudaGetSymbolAddress((void**)&kh,  g_kh);
    cudaGetSymbolAddress((void**)&vh,  g_vh);
    cudaGetSymbolAddress((void**)&ahi, g_ahi);
    cudaGetSymbolAddress((void**)&alo, g_alo);
    cudaGetSymbolAddress((void**)&wqh, g_wqhi);
    cudaGetSymbolAddress((void**)&wql, g_wqlo);
    cudaGetSymbolAddress((void**)&wkh, g_wkhi);
    cudaGetSymbolAddress((void**)&wkl, g_wklo);
    cudaGetSymbolAddress((void**)&wvh, g_wvhi);
    cudaGetSymbolAddress((void**)&wvl, g_wvlo);
    cudaGetSymbolAddress((void**)&woh, g_wohi);
    cudaGetSymbolAddress((void**)&wol, g_wolo);

    cudaFuncSetAttribute(gemm_mma_split<0>,
                         cudaFuncAttributeMaxDynamicSharedMemorySize, GEMM_SMEM);
    cudaFuncSetAttribute(gemm_mma_split<1>,
                         cudaFuncAttributeMaxDynamicSharedMemorySize, GEMM_SMEM);
    cudaFuncSetAttribute(attn_mma,
                         cudaFuncAttributeMaxDynamicSharedMemorySize, ATT_SMEM);

    conv_split<<<(M_*D_/4)/256, 256>>>(x, xhi, xlo, M_*D_/4);
    dim3 gw((D_*D_/4)/256, 4);
    conv_split_w<<<gw, 256>>>(Wq, Wk, Wv, Wo,
                              wqh, wql, wkh, wkl, wvh, wvl, woh, wol);

    dim3 gq(D_/128, M_/128, 3);   // fused QKV
    gemm_mma_split<1><<<gq, 512, GEMM_SMEM>>>(
        xhi, xlo,
        wqh, wql, wkh, wkl, wvh, wvl,
        bq, bk, bv,
        nullptr, qh, kh, vh);

    dim3 ga(S_/128, B_*H_);    // (16, 32)
    attn_mma<<<ga, 256, ATT_SMEM>>>(qh, kh, vh, mask, ahi, alo);

    dim3 gg(D_/128, M_/128, 1);
    gemm_mma_split<0><<<gg, 512, GEMM_SMEM>>>(
        ahi, alo,
        woh, wol, woh, wol, woh, wol,
        bo, bo, bo,
        out, nullptr, nullptr, nullptr);
}

// round 17
// speedup vs baseline: 1.0523x; 1.0523x over previous
#include <cuda_runtime.h>
#include <cuda_fp16.h>
#include <cstdint>
#include <math.h>

#define B_  2
#define S_  2048
#define H_  16
#define DH_ 64
#define D_  1024
#define M_  (B_*S_)   // 4096

// ---------------- scratch (__device__ globals; no allocation allowed) -------
__device__ __half g_xhi[M_*D_],  g_xlo[M_*D_];
__device__ __half g_qh[M_*D_];
__device__ __half g_kh[M_*D_];
__device__ __half g_vh[M_*D_];
__device__ __half g_ahi[M_*D_],  g_alo[M_*D_];
__device__ __half g_wqhi[D_*D_], g_wqlo[D_*D_];
__device__ __half g_wkhi[D_*D_], g_wklo[D_*D_];
__device__ __half g_wvhi[D_*D_], g_wvlo[D_*D_];
__device__ __half g_wohi[D_*D_], g_wolo[D_*D_];

// ---------------- helpers ----------------------------------------------------
__device__ __forceinline__ uint32_t smem_u32(const void* p) {
    uint32_t a;
    asm("{ .reg .u64 t; cvta.to.shared.u64 t, %1; cvt.u32.u64 %0, t; }"
        : "=r"(a) : "l"(p));
    return a;
}
__device__ __forceinline__ void cp_async16(uint32_t saddr, const void* gaddr) {
    asm volatile("cp.async.cg.shared.global [%0], [%1], 16;"
                 :: "r"(saddr), "l"(gaddr) : "memory");
}
#define CP_COMMIT() asm volatile("cp.async.commit_group;" ::: "memory")
#define CP_WAIT(n)  asm volatile("cp.async.wait_group %0;" :: "n"(n) : "memory")

__device__ __forceinline__ void ldsm_x4(uint32_t* r, uint32_t addr) {
    asm volatile("ldmatrix.sync.aligned.m8n8.x4.shared.b16 {%0,%1,%2,%3}, [%4];"
                 : "=r"(r[0]), "=r"(r[1]), "=r"(r[2]), "=r"(r[3]) : "r"(addr));
}
__device__ __forceinline__ void ldsm_x4t(uint32_t* r, uint32_t addr) {
    asm volatile("ldmatrix.sync.aligned.m8n8.x4.trans.shared.b16 {%0,%1,%2,%3}, [%4];"
                 : "=r"(r[0]), "=r"(r[1]), "=r"(r[2]), "=r"(r[3]) : "r"(addr));
}
// fp32-accumulator mma
__device__ __forceinline__ void mma_f16(float* c, const uint32_t* a, const uint32_t* b) {
    asm volatile(
        "mma.sync.aligned.m16n8k16.row.col.f32.f16.f16.f32 "
        "{%0,%1,%2,%3}, {%4,%5,%6,%7}, {%8,%9}, {%0,%1,%2,%3};"
        : "+f"(c[0]), "+f"(c[1]), "+f"(c[2]), "+f"(c[3])
        : "r"(a[0]), "r"(a[1]), "r"(a[2]), "r"(a[3]), "r"(b[0]), "r"(b[1]));
}
// fp16-accumulator mma (packed half2 C/D: reg0 = row r pair, reg1 = row r+8 pair)
__device__ __forceinline__ void mma_f16a(uint32_t* c, const uint32_t* a, const uint32_t* b) {
    asm volatile(
        "mma.sync.aligned.m16n8k16.row.col.f16.f16.f16.f16 "
        "{%0,%1}, {%2,%3,%4,%5}, {%6,%7}, {%0,%1};"
        : "+r"(c[0]), "+r"(c[1])
        : "r"(a[0]), "r"(a[1]), "r"(a[2]), "r"(a[3]), "r"(b[0]), "r"(b[1]));
}
__device__ __forceinline__ float ex2f(float x) {
    float r;
    asm("ex2.approx.f32 %0, %1;" : "=f"(r) : "f"(x));
    return r;
}
__device__ __forceinline__ uint32_t ex2_h2(uint32_t x) {
    uint32_t r;
    asm("ex2.approx.f16x2 %0, %1;" : "=r"(r) : "r"(x));
    return r;
}
__device__ __forceinline__ uint32_t hfma2(uint32_t a, uint32_t b, uint32_t c) {
    uint32_t r;
    asm("fma.rn.f16x2 %0, %1, %2, %3;" : "=r"(r) : "r"(a), "r"(b), "r"(c));
    return r;
}
__device__ __forceinline__ uint32_t hsub2(uint32_t a, uint32_t b) {
    uint32_t r;
    asm("sub.f16x2 %0, %1, %2;" : "=r"(r) : "r"(a), "r"(b));
    return r;
}
__device__ __forceinline__ uint32_t hmax2(uint32_t a, uint32_t b) {
    uint32_t r;
    asm("max.f16x2 %0, %1, %2;" : "=r"(r) : "r"(a), "r"(b));
    return r;
}
__device__ __forceinline__ void split2h(float x0, float x1, uint32_t& hi, uint32_t& lo) {
    __half h0 = __float2half_rn(x0);
    __half h1 = __float2half_rn(x1);
    __half l0 = __float2half_rn(x0 - __half2float(h0));
    __half l1 = __float2half_rn(x1 - __half2float(h1));
    hi = (uint32_t)__half_as_ushort(h0) | ((uint32_t)__half_as_ushort(h1) << 16);
    lo = (uint32_t)__half_as_ushort(l0) | ((uint32_t)__half_as_ushort(l1) << 16);
}
__device__ __forceinline__ uint32_t pack2h(float x0, float x1) {
    uint32_t r;
    asm("cvt.rn.f16x2.f32 %0, %1, %2;" : "=r"(r) : "f"(x1), "f"(x0));
    return r;
}

// ---------------- conversions --------------------------------------------------
__global__ __launch_bounds__(256) void conv_split(
    const float* __restrict__ x, __half* __restrict__ hi,
    __half* __restrict__ lo, int n4)
{
    int i = blockIdx.x * blockDim.x + threadIdx.x;
    if (i >= n4) return;
    float4 v = ((const float4*)x)[i];
    uint32_t h0, l0, h1, l1;
    split2h(v.x, v.y, h0, l0);
    split2h(v.z, v.w, h1, l1);
    uint2 ho = { h0, h1 }, loo = { l0, l1 };
    ((uint2*)hi)[i] = ho;
    ((uint2*)lo)[i] = loo;
}

__global__ __launch_bounds__(256) void conv_split_w(
    const float* w0, const float* w1, const float* w2, const float* w3,
    __half* h0, __half* l0, __half* h1, __half* l1,
    __half* h2, __half* l2, __half* h3, __half* l3)
{
    const float* x; __half* hi; __half* lo;
    if      (blockIdx.y == 0) { x = w0; hi = h0; lo = l0; }
    else if (blockIdx.y == 1) { x = w1; hi = h1; lo = l1; }
    else if (blockIdx.y == 2) { x = w2; hi = h2; lo = l2; }
    else                      { x = w3; hi = h3; lo = l3; }
    int i = blockIdx.x * blockDim.x + threadIdx.x;
    if (i >= D_*D_/4) return;
    float4 v = ((const float4*)x)[i];
    uint32_t a0, b0, a1, b1;
    split2h(v.x, v.y, a0, b0);
    split2h(v.z, v.w, a1, b1);
    uint2 ho = { a0, a1 }, loo = { b0, b1 };
    ((uint2*)hi)[i] = ho;
    ((uint2*)lo)[i] = loo;
}

// ---------------- mma.sync 3-pass fp16 GEMM (R15 schedule; lo-passes f16-acc) --
// C = Ahi*Whi (fp32 acc) + [Ahi*Wlo + Alo*Whi] (fp16 acc, added at epilogue).
// 512 threads, 16 warps (4m x 4n), warp 32x32, BK=32 halves, 4-stage cp.async.
#define BKH     32
#define MAT_B   (128*64)
#define STAGE_B (4*MAT_B)
#define NSTAGE  4
#define GEMM_SMEM (NSTAGE*STAGE_B)  // 131072

template <int MODE>
__global__ __launch_bounds__(512, 1) void gemm_mma_split(
    const __half* __restrict__ Ahi, const __half* __restrict__ Alo,
    const __half* __restrict__ Wh0, const __half* __restrict__ Wl0,
    const __half* __restrict__ Wh1, const __half* __restrict__ Wl1,
    const __half* __restrict__ Wh2, const __half* __restrict__ Wl2,
    const float* __restrict__ b0p, const float* __restrict__ b1p,
    const float* __restrict__ b2p,
    float* __restrict__ C,
    __half* __restrict__ C0, __half* __restrict__ C1, __half* __restrict__ C2)
{
    const __half* Whi; const __half* Wlo; const float* bias; __half* Ch;
    if      (blockIdx.z == 0) { Whi = Wh0; Wlo = Wl0; bias = b0p; Ch = C0; }
    else if (blockIdx.z == 1) { Whi = Wh1; Wlo = Wl1; bias = b1p; Ch = C1; }
    else                      { Whi = Wh2; Wlo = Wl2; bias = b2p; Ch = C2; }

    extern __shared__ __align__(1024) char smraw[];
    const uint32_t sb = smem_u32(smraw);

    const int tid = threadIdx.x;
    const int wid = tid >> 5;
    const int l   = tid & 31;
    const int wm  = wid & 3;
    const int wn  = wid >> 2;
    const int m0  = blockIdx.y * 128;
    const int n0  = blockIdx.x * 128;

    const int crow = tid >> 2;
    const int cch  = tid & 3;
    const uint32_t sst = (uint32_t)(crow * 64 + ((cch ^ ((crow >> 1) & 3)) << 4));
    const __half* gAh = Ahi + (size_t)(m0 + crow) * D_ + cch * 8;
    const __half* gAl = Alo + (size_t)(m0 + crow) * D_ + cch * 8;
    const __half* gWh = Whi + (size_t)(n0 + crow) * D_ + cch * 8;
    const __half* gWl = Wlo + (size_t)(n0 + crow) * D_ + cch * 8;

    const int rA  = wm * 32 + (l & 15);
    const int xkA = (rA >> 1) & 3;
    const int cA  = l >> 4;
    const uint32_t aA_k0 = (uint32_t)(rA * 64 + ((cA       ^ xkA) << 4));
    const uint32_t aA_k1 = (uint32_t)(rA * 64 + (((cA + 2) ^ xkA) << 4));
    const int rB  = wn * 32 + (l & 7) + ((l >> 4) << 3);
    const int xkB = (rB >> 1) & 3;
    const int cB  = (l >> 3) & 1;
    const uint32_t aB_k0 = (uint32_t)(rB * 64 + ((cB       ^ xkB) << 4));
    const uint32_t aB_k1 = (uint32_t)(rB * 64 + (((cB + 2) ^ xkB) << 4));

    float acc[2][4][4];
    uint32_t accl[2][4][2];
#pragma unroll
    for (int mt = 0; mt < 2; mt++)
#pragma unroll
        for (int nt = 0; nt < 4; nt++) {
#pragma unroll
            for (int e = 0; e < 4; e++) acc[mt][nt][e] = 0.f;
            accl[mt][nt][0] = 0u; accl[mt][nt][1] = 0u;
        }

    const int NKT = D_ / BKH;

    auto issue_stage = [&](int s) {
        const uint32_t d = sb + (s & (NSTAGE-1)) * STAGE_B + sst;
        const int off = s * BKH;
        cp_async16(d + 0*MAT_B, gAh + off);
        cp_async16(d + 1*MAT_B, gAl + off);
        cp_async16(d + 2*MAT_B, gWh + off);
        cp_async16(d + 3*MAT_B, gWl + off);
    };

    issue_stage(0); CP_COMMIT();
    issue_stage(1); CP_COMMIT();
    issue_stage(2); CP_COMMIT();

    for (int kt = 0; kt < NKT; kt++) {
        if (kt + 3 < NKT) issue_stage(kt + 3);
        CP_COMMIT();
        CP_WAIT(3);
        __syncthreads();

        const uint32_t base = sb + (kt & (NSTAGE-1)) * STAGE_B;

#pragma unroll
        for (int kk = 0; kk < 2; kk++) {
            const uint32_t aA = base + (kk ? aA_k1 : aA_k0);
            const uint32_t aB = base + (kk ? aB_k1 : aB_k0);

            uint32_t ah[2][4];
            ldsm_x4(ah[0], aA + 0*MAT_B);
            ldsm_x4(ah[1], aA + 0*MAT_B + 1024);
            uint32_t wh[2][4];
            ldsm_x4(wh[0], aB + 2*MAT_B);
            ldsm_x4(wh[1], aB + 2*MAT_B + 1024);
            // pass 1: Ahi*Whi, fp32 accumulators
#pragma unroll
            for (int mt = 0; mt < 2; mt++)
#pragma unroll
                for (int nt = 0; nt < 4; nt++)
                    mma_f16(acc[mt][nt], ah[mt], &wh[nt >> 1][(nt & 1) * 2]);

            uint32_t wl[2][4];
            ldsm_x4(wl[0], aB + 3*MAT_B);
            ldsm_x4(wl[1], aB + 3*MAT_B + 1024);
            // pass 2: Ahi*Wlo, fp16 accumulators
#pragma unroll
            for (int mt = 0; mt < 2; mt++)
#pragma unroll
                for (int nt = 0; nt < 4; nt++)
                    mma_f16a(accl[mt][nt], ah[mt], &wl[nt >> 1][(nt & 1) * 2]);

            uint32_t al[2][4];
            ldsm_x4(al[0], aA + 1*MAT_B);
            ldsm_x4(al[1], aA + 1*MAT_B + 1024);
            // pass 3: Alo*Whi, fp16 accumulators
#pragma unroll
            for (int mt = 0; mt < 2; mt++)
#pragma unroll
                for (int nt = 0; nt < 4; nt++)
                    mma_f16a(accl[mt][nt], al[mt], &wh[nt >> 1][(nt & 1) * 2]);
        }

        __syncthreads();
    }

    const int rbase = m0 + wm*32 + (l >> 2);
    const int cbase = n0 + wn*32 + (l & 3) * 2;
#pragma unroll
    for (int mt = 0; mt < 2; mt++) {
#pragma unroll
        for (int nt = 0; nt < 4; nt++) {
            const int col = cbase + nt * 8;
            const float b0 = bias[col], b1 = bias[col + 1];
            const float2 lo01 = __half22float2(*reinterpret_cast<__half2*>(&accl[mt][nt][0]));
            const float2 lo23 = __half22float2(*reinterpret_cast<__half2*>(&accl[mt][nt][1]));
            const float d0 = acc[mt][nt][0] + lo01.x + b0;
            const float d1 = acc[mt][nt][1] + lo01.y + b1;
            const float d2 = acc[mt][nt][2] + lo23.x + b0;
            const float d3 = acc[mt][nt][3] + lo23.y + b1;
            const size_t r0o = (size_t)(rbase + mt*16) * D_ + col;
            const size_t r1o = (size_t)(rbase + mt*16 + 8) * D_ + col;
            if (MODE == 1) {
                *(uint32_t*)(Ch + r0o) = pack2h(d0, d1);
                *(uint32_t*)(Ch + r1o) = pack2h(d2, d3);
            } else {
                float2 v0 = { d0, d1 };
                float2 v1 = { d2, d3 };
                *(float2*)(C + r0o) = v0;
                *(float2*)(C + r1o) = v1;
            }
        }
    }
}

// ---------------- fp16 flash attention: f16-acc QK + packed softmax ------------
// QK accumulates directly in packed fp16 (D fragment == pw layout): no pack2h.
// mask+scale fma.f16x2, max.f16x2 row max, sub+ex2.f16x2 -> PV fragments.
// Row sums via ones-mma (fp32 acc, rides alpha rescale).
#define AT_QP 72
#define oQ 0
#define oK 18432
#define oV 36864
#define oM 55296
#define ATT_SMEM (oM + S_*2)   // 59392

__global__ __launch_bounds__(256, 2) void attn_mma(
    const __half* __restrict__ Qh, const __half* __restrict__ Kh,
    const __half* __restrict__ Vh, const int* __restrict__ mask,
    __half* __restrict__ Ah, __half* __restrict__ Al)
{
    extern __shared__ __align__(1024) char sm[];
    const uint32_t sb = smem_u32(sm);
    uint32_t* Mh2 = (uint32_t*)(sm + oM);

    const int tid = threadIdx.x;
    const int wid = tid >> 5;
    const int l   = tid & 31;
    const int b   = blockIdx.y >> 4;
    const int h   = blockIdx.y & 15;
    const int q0  = blockIdx.x * 128;

    const int crow = tid >> 1, chc = (tid & 1) * 32;
    const uint32_t cds = (uint32_t)(crow * AT_QP + chc) * 2;
    const size_t gKVrow = (size_t)(b*S_ + crow) * D_ + h*DH_ + chc;

    auto issue_K = [&](int kt) {
        const size_t g = gKVrow + (size_t)kt * 128 * D_;
#pragma unroll
        for (int j = 0; j < 4; j++)
            cp_async16(sb + oK + cds + j*16, Kh + g + j*8);
    };
    auto issue_V = [&](int kt) {
        const size_t g = gKVrow + (size_t)kt * 128 * D_;
#pragma unroll
        for (int j = 0; j < 4; j++)
            cp_async16(sb + oV + cds + j*16, Vh + g + j*8);
    };

    for (int i = tid; i < S_/2; i += 256) {
        const int2 mv = *(const int2*)(mask + (size_t)b*S_ + 2*i);
        uint32_t w = (mv.x ? 0u : 0xFC00u) | ((mv.y ? 0u : 0xFC00u) << 16);
        Mh2[i] = w;
    }

    {
        const size_t g = (size_t)(b*S_ + q0 + crow) * D_ + h*DH_ + chc;
#pragma unroll
        for (int j = 0; j < 4; j++)
            cp_async16(sb + oQ + cds + j*16, Qh + g + j*8);
    }
    issue_K(0);
    CP_COMMIT();
    issue_V(0);
    CP_COMMIT();

    float m_run[2] = { -1e30f, -1e30f };
    float o[8][4];
    float o_sum[4] = { 0.f, 0.f, 0.f, 0.f };
#pragma unroll
    for (int nt = 0; nt < 8; nt++)
#pragma unroll
        for (int e = 0; e < 4; e++) o[nt][e] = 0.f;

    const uint32_t ones2[2] = { 0x3C003C00u, 0x3C003C00u };

    const uint32_t aQ  = sb + oQ + (uint32_t)(((wid<<4) + (l & 15)) * AT_QP + ((l >> 4) << 3)) * 2;
    const uint32_t aKo = (uint32_t)(((l & 7) + ((l >> 4) << 3)) * AT_QP + (((l >> 3) & 1) << 3)) * 2;
    const uint32_t aVo = (uint32_t)(((l & 7) + (((l >> 3) & 1) << 3)) * AT_QP + ((l >> 4) << 3)) * 2;

    const float KSC = 0.125f * 1.44269504f;
    const uint32_t KSC2 = pack2h(KSC, KSC);

    for (int kt = 0; kt < S_/128; kt++) {
        CP_WAIT(1);
        __syncthreads();

        // ---- QK^T with fp16 accumulators: pw[nt] = packed score pairs ----
        uint32_t pw[16][2];
#pragma unroll
        for (int nt = 0; nt < 16; nt++) { pw[nt][0] = 0u; pw[nt][1] = 0u; }

#pragma unroll
        for (int ks = 0; ks < 4; ks++) {
            uint32_t q[4];
            ldsm_x4(q, aQ + ks*32);
#pragma unroll
            for (int np = 0; np < 8; np++) {
                uint32_t k[4];
                ldsm_x4(k, sb + oK + aKo + np*(16*AT_QP*2) + ks*32);
                mma_f16a(pw[2*np],   q, k);
                mma_f16a(pw[2*np+1], q, k+2);
            }
        }

        // ---- packed mask+scale + row max ----
        const int mb = kt * 64 + (l & 3);
        uint32_t mxp0 = 0xFC00FC00u, mxp1 = 0xFC00FC00u;
#pragma unroll
        for (int nt = 0; nt < 16; nt++) {
            const uint32_t m2 = Mh2[mb + nt*4];
            pw[nt][0] = hfma2(pw[nt][0], KSC2, m2);
            pw[nt][1] = hfma2(pw[nt][1], KSC2, m2);
            mxp0 = hmax2(mxp0, pw[nt][0]);
            mxp1 = hmax2(mxp1, pw[nt][1]);
        }
        __half2 hx0 = *reinterpret_cast<__half2*>(&mxp0);
        __half2 hx1 = *reinterpret_cast<__half2*>(&mxp1);
        float mx0 = fmaxf(__low2float(hx0), __high2float(hx0));
        float mx1 = fmaxf(__low2float(hx1), __high2float(hx1));
        mx0 = fmaxf(mx0, __shfl_xor_sync(0xffffffffu, mx0, 1));
        mx0 = fmaxf(mx0, __shfl_xor_sync(0xffffffffu, mx0, 2));
        mx1 = fmaxf(mx1, __shfl_xor_sync(0xffffffffu, mx1, 1));
        mx1 = fmaxf(mx1, __shfl_xor_sync(0xffffffffu, mx1, 2));

        const float mn0 = fmaxf(m_run[0], mx0);
        const float mn1 = fmaxf(m_run[1], mx1);
        const float al0 = ex2f(m_run[0] - mn0);
        const float al1 = ex2f(m_run[1] - mn1);
        m_run[0] = mn0; m_run[1] = mn1;

        // ---- P = 2^(w - mn) ----
        const uint32_t mn0h = pack2h(mn0, mn0);
        const uint32_t mn1h = pack2h(mn1, mn1);
#pragma unroll
        for (int nt = 0; nt < 16; nt++) {
            pw[nt][0] = ex2_h2(hsub2(pw[nt][0], mn0h));
            pw[nt][1] = ex2_h2(hsub2(pw[nt][1], mn1h));
        }

        // ---- alpha rescale ----
#pragma unroll
        for (int nt = 0; nt < 8; nt++) {
            o[nt][0] *= al0; o[nt][1] *= al0;
            o[nt][2] *= al1; o[nt][3] *= al1;
        }
        o_sum[0] *= al0; o_sum[1] *= al0;
        o_sum[2] *= al1; o_sum[3] *= al1;

        CP_WAIT(0);
        __syncthreads();

        if (kt + 1 < S_/128) issue_K(kt + 1);
        CP_COMMIT();

        // ---- PV + ones-mma row sum ----
#pragma unroll
        for (int ks = 0; ks < 8; ks++) {
            uint32_t p[4] = { pw[2*ks][0], pw[2*ks][1], pw[2*ks+1][0], pw[2*ks+1][1] };
            mma_f16(o_sum, p, ones2);
#pragma unroll
            for (int vb = 0; vb < 4; vb++) {
                uint32_t v[4];
                ldsm_x4t(v, sb + oV + aVo + ks*(16*AT_QP*2) + vb*32);
                mma_f16(o[2*vb],   p, v);
                mma_f16(o[2*vb+1], p, v+2);
            }
        }

        __syncthreads();
        if (kt + 1 < S_/128) issue_V(kt + 1);
        CP_COMMIT();
    }

    const float i0 = 1.f / o_sum[0];
    const float i1 = 1.f / o_sum[2];
    const int   c0 = (l & 3) * 2;
    const size_t row0 = (size_t)(b*S_ + q0 + (wid<<4) + (l >> 2));
    const size_t row1 = row0 + 8;
#pragma unroll
    for (int nt = 0; nt < 8; nt++) {
        const int col = h*DH_ + nt*8 + c0;
        uint32_t hi, lo;
        split2h(o[nt][0]*i0, o[nt][1]*i0, hi, lo);
        *(uint32_t*)(Ah + row0*D_ + col) = hi;
        *(uint32_t*)(Al + row0*D_ + col) = lo;
        split2h(o[nt][2]*i1, o[nt][3]*i1, hi, lo);
        *(uint32_t*)(Ah + row1*D_ + col) = hi;
        *(uint32_t*)(Al + row1*D_ + col) = lo;
    }
}

// ---------------------------------------------------------------------------
extern "C" void kernel_launch(void* const* d_in, const int* in_sizes, int n_in,
                              void* d_out, int out_size)
{
    const float* x    = (const float*)d_in[0];
    const int*   mask = (const int*)  d_in[1];
    const float* Wq   = (const float*)d_in[2];
    const float* bq   = (const float*)d_in[3];
    const float* Wk   = (const float*)d_in[4];
    const float* bk   = (const float*)d_in[5];
    const float* Wv   = (const float*)d_in[6];
    const float* bv   = (const float*)d_in[7];
    const float* Wo   = (const float*)d_in[8];
    const float* bo   = (const float*)d_in[9];
    float* out = (float*)d_out;

    __half *xhi, *xlo, *qh, *kh, *vh, *ahi, *alo;
    __half *wqh, *wql, *wkh, *wkl, *wvh, *wvl, *woh, *wol;
    cudaGetSymbolAddress((void**)&xhi, g_xhi);
    cudaGetSymbolAddress((void**)&xlo, g_xlo);
    cudaGetSymbolAddress((void**)&qh,  g_qh);
    cudaGetSymbolAddress((void**)&kh,  g_kh);
    cudaGetSymbolAddress((void**)&vh,  g_vh);
    cudaGetSymbolAddress((void**)&ahi, g_ahi);
    cudaGetSymbolAddress((void**)&alo, g_alo);
    cudaGetSymbolAddress((void**)&wqh, g_wqhi);
    cudaGetSymbolAddress((void**)&wql, g_wqlo);
    cudaGetSymbolAddress((void**)&wkh, g_wkhi);
    cudaGetSymbolAddress((void**)&wkl, g_wklo);
    cudaGetSymbolAddress((void**)&wvh, g_wvhi);
    cudaGetSymbolAddress((void**)&wvl, g_wvlo);
    cudaGetSymbolAddress((void**)&woh, g_wohi);
    cudaGetSymbolAddress((void**)&wol, g_wolo);

    cudaFuncSetAttribute(gemm_mma_split<0>,
                         cudaFuncAttributeMaxDynamicSharedMemorySize, GEMM_SMEM);
    cudaFuncSetAttribute(gemm_mma_split<1>,
                         cudaFuncAttributeMaxDynamicSharedMemorySize, GEMM_SMEM);
    cudaFuncSetAttribute(attn_mma,
                         cudaFuncAttributeMaxDynamicSharedMemorySize, ATT_SMEM);

    conv_split<<<(M_*D_/4)/256, 256>>>(x, xhi, xlo, M_*D_/4);
    dim3 gw((D_*D_/4)/256, 4);
    conv_split_w<<<gw, 256>>>(Wq, Wk, Wv, Wo,
                              wqh, wql, wkh, wkl, wvh, wvl, woh, wol);

    dim3 gq(D_/128, M_/128, 3);   // fused QKV
    gemm_mma_split<1><<<gq, 512, GEMM_SMEM>>>(
        xhi, xlo,
        wqh, wql, wkh, wkl, wvh, wvl,
        bq, bk, bv,
        nullptr, qh, kh, vh);

    dim3 ga(S_/128, B_*H_);    // (16, 32)
    attn_mma<<<ga, 256, ATT_SMEM>>>(qh, kh, vh, mask, ahi, alo);

    dim3 gg(D_/128, M_/128, 1);
    gemm_mma_split<0><<<gg, 512, GEMM_SMEM>>>(
        ahi, alo,
        woh, wol, woh, wol, woh, wol,
        bo, bo, bo,
        out, nullptr, nullptr, nullptr);
}